// round 8
// baseline (speedup 1.0000x reference)
#include <cuda_runtime.h>
#include <math.h>

#define HW    128
#define CIN   256
#define DLOI  128
#define NB    8
#define NL    2048
#define NLINES (NB*NL)
#define BN_EPS 1e-5f

// Scratch: fc1 output in NHWC layout [b][i][j][o]  (64 MB)
__device__ float g_x[(size_t)NB * HW * HW * DLOI];
// Pre-transformed weights (written by k_prep each launch)
__device__ float g_w1dup[256 * 256];      // fc1 W: [k][o*2] dup'd pairs
__device__ float g_w1d[128 * 64 * 2];     // conv1 [c][p] dup'd
__device__ float g_w2d[192 * 64 * 2];     // conv2 [(i*3+dt)][q] dup'd
__device__ float g_w3d[64 * 128 * 2];     // conv3 [q][o] dup'd
__device__ float g_const[1792];           // biases / bn scale+offset / fc2w

// ---- packed f32x2 helpers (sm_103a dual-fp32 pipe) ----
typedef unsigned long long u64;

__device__ __forceinline__ u64 dup2(float x) {
    u64 r; asm("mov.b64 %0, {%1, %1};" : "=l"(r) : "f"(x)); return r;
}
__device__ __forceinline__ float2 unpack2(u64 v) {
    float2 f; asm("mov.b64 {%0, %1}, %2;" : "=f"(f.x), "=f"(f.y) : "l"(v)); return f;
}
__device__ __forceinline__ void fma2(u64& d, u64 a, u64 b) {
    asm("fma.rn.f32x2 %0, %1, %2, %0;" : "+l"(d) : "l"(a), "l"(b));
}
__device__ __forceinline__ void cp16(void* smem_dst, const void* gsrc) {
    unsigned s = (unsigned)__cvta_generic_to_shared(smem_dst);
    asm volatile("cp.async.ca.shared.global [%0], [%1], 16;" :: "r"(s), "l"(gsrc) : "memory");
}
__device__ __forceinline__ void cp_commit() {
    asm volatile("cp.async.commit_group;" ::: "memory");
}
__device__ __forceinline__ void cp_wait0() {
    asm volatile("cp.async.wait_group 0;" ::: "memory");
}

// stage NF floats (multiple of 1024) into smem and wait
template <int NF>
__device__ __forceinline__ void stage_w(float* dst, const float* src, int tid) {
#pragma unroll
    for (int r = 0; r < NF / 1024; r++) {
        int c = (tid + r * 256) * 4;
        cp16(dst + c, src + c);
    }
    cp_commit();
    cp_wait0();
}

// ---------------------------------------------------------------------------
// K0: weight pre-transform (runs once per launch, trivial cost)
// ---------------------------------------------------------------------------
__global__ void k_prep(const float* __restrict__ fc1w,
                       const float* __restrict__ bn1g, const float* __restrict__ bn1b,
                       const float* __restrict__ bn1m, const float* __restrict__ bn1v,
                       const float* __restrict__ c1w,  const float* __restrict__ c1b,
                       const float* __restrict__ bn2g, const float* __restrict__ bn2b,
                       const float* __restrict__ bn2m, const float* __restrict__ bn2v,
                       const float* __restrict__ c2w,  const float* __restrict__ c2b,
                       const float* __restrict__ bn3g, const float* __restrict__ bn3b,
                       const float* __restrict__ bn3m, const float* __restrict__ bn3v,
                       const float* __restrict__ c3w,  const float* __restrict__ c3b,
                       const float* __restrict__ fc2w) {
    const int tid = blockIdx.x * 256 + threadIdx.x;
    const int STR = gridDim.x * 256;
    for (int i = tid; i < 128 * 256; i += STR) {     // [k][o*2] <- fc1w[o][k]
        int o = i >> 8, k = i & 255;
        float v = fc1w[i];
        g_w1dup[k * 256 + o * 2]     = v;
        g_w1dup[k * 256 + o * 2 + 1] = v;
    }
    for (int i = tid; i < 8192; i += STR) {          // [c][p] dup <- c1w[p][c]
        int p = i & 63, c = i >> 6;
        float v = c1w[p * 128 + c];
        g_w1d[i * 2]     = v;
        g_w1d[i * 2 + 1] = v;
    }
    for (int i = tid; i < 12288; i += STR) {         // [(i3)][q] dup <- c2w[q][i3]
        int q = i & 63, i3 = i >> 6;
        float v = c2w[q * 192 + i3];
        g_w2d[i * 2]     = v;
        g_w2d[i * 2 + 1] = v;
    }
    for (int i = tid; i < 8192; i += STR) {          // [q][o] dup <- c3w[o][q]
        int o = i & 127, q = i >> 7;
        float v = c3w[o * 64 + q];
        g_w3d[i * 2]     = v;
        g_w3d[i * 2 + 1] = v;
    }
    if (tid < 64) {
        float s2 = bn2g[tid] * rsqrtf(bn2v[tid] + BN_EPS);
        g_const[64 + tid]  = s2;
        g_const[128 + tid] = bn2b[tid] - bn2m[tid] * s2;
        g_const[tid]       = c1b[tid];
        float s3 = bn3g[tid] * rsqrtf(bn3v[tid] + BN_EPS);
        g_const[256 + tid] = s3;
        g_const[320 + tid] = bn3b[tid] - bn3m[tid] * s3;
        g_const[192 + tid] = c2b[tid];
    } else if (tid < 192) {
        int t2 = tid - 64;
        g_const[384 + t2] = c3b[t2];
        float s1 = bn1g[t2] * rsqrtf(bn1v[t2] + BN_EPS);
        g_const[512 + t2] = s1;
        g_const[640 + t2] = bn1b[t2] - bn1m[t2] * s1;
    }
    for (int i = tid; i < 1024; i += STR) g_const[768 + i] = fc2w[i];
}

// ---------------------------------------------------------------------------
// K1: fc1 SGEMM, f32x2, warp-broadcast W.
// Block 128pix x 128out, 256 threads = 8 warps.  Warp w -> outputs
// [w*16, w*16+16); lane -> pixels [lane*4, lane*4+4).  W reads are LDS.128
// broadcasts; A reads lane-consecutive.  cp.async 3-stage pipeline.
// ---------------------------------------------------------------------------
#define KT 16
#define NT (CIN / KT)
#define SA_OF(s,k) ((s)*2048 + (k)*128)
#define SW_OF(s,k) (6144 + (s)*4096 + (k)*256)
#define FC1_SMEM_FLOATS (6144 + 3*4096)
#define FC1_SMEM_BYTES  (FC1_SMEM_FLOATS * 4)

__global__ __launch_bounds__(256, 2) void k_fc1(const float* __restrict__ feat,
                                                const float* __restrict__ bias) {
    extern __shared__ float smem[];
    const int b = blockIdx.y;
    const int pixbase = blockIdx.x * 128;
    const int tid = threadIdx.x;
    const int w = tid >> 5;       // warp -> o0 = w*16
    const int lane = tid & 31;    // lane -> pix0 = lane*4

    const float* fb = feat + (size_t)b * CIN * HW * HW + pixbase;

    u64 acc[2][16];               // [pix-pair][o]
#pragma unroll
    for (int i = 0; i < 2; i++)
#pragma unroll
        for (int j = 0; j < 16; j++) acc[i][j] = 0ULL;

#define PREF(t, s) do {                                                        \
        int i0 = tid, i1 = tid + 256;          /* A: 512 chunks of 16B */      \
        cp16(smem + SA_OF(s, i0 >> 5) + (i0 & 31) * 4,                         \
             fb + (size_t)((t)*KT + (i0 >> 5)) * (HW*HW) + (i0 & 31) * 4);     \
        cp16(smem + SA_OF(s, i1 >> 5) + (i1 & 31) * 4,                         \
             fb + (size_t)((t)*KT + (i1 >> 5)) * (HW*HW) + (i1 & 31) * 4);     \
        _Pragma("unroll")                                                      \
        for (int r = 0; r < 4; r++) {          /* W: 1024 chunks of 16B */     \
            int c = tid + r * 256;                                             \
            cp16(smem + SW_OF(s, 0) + c * 4,                                   \
                 g_w1dup + (size_t)(t) * 4096 + c * 4);                        \
        }                                                                      \
    } while (0)

    PREF(0, 0); cp_commit();
    PREF(1, 1); cp_commit();

#pragma unroll 1
    for (int t = 0; t < NT; t++) {
        if (t < NT - 1)
            asm volatile("cp.async.wait_group 1;" ::: "memory");
        else
            asm volatile("cp.async.wait_group 0;" ::: "memory");
        __syncthreads();
        if (t + 2 < NT) {
            int s = (t + 2) % 3;
            PREF(t + 2, s); cp_commit();
        }
        const int s = t % 3;
#pragma unroll
        for (int k = 0; k < KT; k++) {
            ulonglong2 av2 = *(const ulonglong2*)(smem + SA_OF(s, k) + lane * 4);
            u64 av[2] = {av2.x, av2.y};
            const ulonglong2* wp =
                (const ulonglong2*)(smem + SW_OF(s, k) + w * 32);
#pragma unroll
            for (int h = 0; h < 2; h++) {
                ulonglong2 q0 = wp[h * 4 + 0], q1 = wp[h * 4 + 1];
                ulonglong2 q2 = wp[h * 4 + 2], q3 = wp[h * 4 + 3];
                u64 wv[8] = {q0.x, q0.y, q1.x, q1.y, q2.x, q2.y, q3.x, q3.y};
#pragma unroll
                for (int i = 0; i < 2; i++)
#pragma unroll
                    for (int j = 0; j < 8; j++)
                        fma2(acc[i][h * 8 + j], av[i], wv[j]);
            }
        }
    }
#undef PREF

    float bv[16];
#pragma unroll
    for (int j = 0; j < 16; j++) bv[j] = bias[w * 16 + j];
#pragma unroll
    for (int i = 0; i < 2; i++) {
        float2 vj[16];
#pragma unroll
        for (int j = 0; j < 16; j++) vj[j] = unpack2(acc[i][j]);
        size_t pix0 = (size_t)pixbase + lane * 4 + 2 * i;
        float* d0 = &g_x[((size_t)b * (HW * HW) + pix0) * DLOI + w * 16];
        float* d1 = d0 + DLOI;
#pragma unroll
        for (int r = 0; r < 4; r++) {
            *(float4*)(d0 + r * 4) = make_float4(
                vj[r * 4 + 0].x + bv[r * 4 + 0], vj[r * 4 + 1].x + bv[r * 4 + 1],
                vj[r * 4 + 2].x + bv[r * 4 + 2], vj[r * 4 + 3].x + bv[r * 4 + 3]);
            *(float4*)(d1 + r * 4) = make_float4(
                vj[r * 4 + 0].y + bv[r * 4 + 0], vj[r * 4 + 1].y + bv[r * 4 + 1],
                vj[r * 4 + 2].y + bv[r * 4 + 2], vj[r * 4 + 3].y + bv[r * 4 + 3]);
        }
    }
}

// ---------------------------------------------------------------------------
// K2: fused sampling + bn1/relu + Bottleneck1D + residual + fc2.
// 4 lines per block, 256 threads.  Weights streamed PRE-DUPLICATED through an
// 8192-float WBUF (no dup MOVs in conv loops).  91KB smem -> 2 blocks/SM.
// ---------------------------------------------------------------------------
#define L_WBUF  0        // 8192  streamed dup'd weight chunks
#define L_XP    8192     // 4096  [ln][c][t]
#define L_A     12288    // 4096  a = relu(bn1(xp)); C aliases
#define L_C     12288
#define L_B1    16384    // 3072  [ln*64+p]*12 zero-padded; TBL/RED alias
#define L_TBL   16384
#define L_RED   16384
#define L_B2    19456    // 2048  [ln*64+p]*8 unpadded copy
#define L_CONST 21504    // 1792
#define K2_SMEM_FLOATS 23296
#define K2_SMEM_BYTES  (K2_SMEM_FLOATS * 4)

__global__ void __launch_bounds__(256, 2) k_lines(
    const float* __restrict__ lines,
    const float* __restrict__ fc2b,
    float* __restrict__ out)
{
    extern __shared__ float sm[];
    const int tid = threadIdx.x;
    const int n0 = blockIdx.x * 4;

    // ---- issue W1 chunk 0 (dup'd, 8192 floats) early; wait deferred ----
#pragma unroll
    for (int r = 0; r < 8; r++) {
        int c = (tid + r * 256) * 4;
        cp16(sm + L_WBUF + c, g_w1d + c);
    }
    cp_commit();

    // ---- consts + sampling tables ----
    {
        float4* cd = (float4*)(sm + L_CONST);
        const float4* cs = (const float4*)g_const;
        cd[tid] = cs[tid];
        if (tid < 192) cd[tid + 256] = cs[tid + 256];
    }
    if (tid < 128) {
        int ln = tid >> 5, p = tid & 31;
        const float* lp = lines + (size_t)(n0 + ln) * 4;
        float lam = (float)p * (1.0f / 31.0f);
        float px = lp[0] * lam + lp[2] * (1.f - lam) - 0.5f;
        float py = lp[1] * lam + lp[3] * (1.f - lam) - 0.5f;
        float px0 = fminf(fmaxf(floorf(px), 0.f), 127.f);
        float py0 = fminf(fmaxf(floorf(py), 0.f), 127.f);
        float px1 = fminf(px0 + 1.f, 127.f);
        float py1 = fminf(py0 + 1.f, 127.f);
        int ix0 = (int)px0, iy0 = (int)py0, ix1 = (int)px1, iy1 = (int)py1;
        u64* wtb = (u64*)(sm + L_TBL);
        wtb[0 * 128 + tid] = dup2((px1 - px) * (py1 - py));
        wtb[1 * 128 + tid] = dup2((px - px0) * (py1 - py));
        wtb[2 * 128 + tid] = dup2((px1 - px) * (py - py0));
        wtb[3 * 128 + tid] = dup2((px - px0) * (py - py0));
        int* ofb = (int*)(sm + L_TBL + 1024);
        ofb[0 * 128 + tid] = (ix0 * HW + iy0) * (DLOI / 2);
        ofb[1 * 128 + tid] = (ix1 * HW + iy0) * (DLOI / 2);
        ofb[2 * 128 + tid] = (ix0 * HW + iy1) * (DLOI / 2);
        ofb[3 * 128 + tid] = (ix1 * HW + iy1) * (DLOI / 2);
    }
    __syncthreads();

    const int ln = tid >> 6;

    // ---- sampling + maxpool + fused bn1/relu ----
    {
        int cp = tid & 63, c0 = cp * 2;
        int bb = n0 >> 11;
        const u64* basep = (const u64*)g_x + (size_t)bb * (HW * HW) * (DLOI / 2) + cp;
        const u64* wtb = (const u64*)(sm + L_TBL);
        const int* ofb = (const int*)(sm + L_TBL + 1024);
        float v0[8], v1[8];
#pragma unroll
        for (int t = 0; t < 8; t++) {
            float m0 = -3.4e38f, m1 = -3.4e38f;
#pragma unroll
            for (int j = 0; j < 4; j++) {
                int idx = ln * 32 + t * 4 + j;
                u64 acc = 0ULL;
#pragma unroll
                for (int cn = 0; cn < 4; cn++) {
                    u64 wv = wtb[cn * 128 + idx];
                    u64 xv = basep[ofb[cn * 128 + idx]];
                    fma2(acc, wv, xv);
                }
                float2 s = unpack2(acc);
                m0 = fmaxf(m0, s.x);
                m1 = fmaxf(m1, s.y);
            }
            v0[t] = m0; v1[t] = m1;
        }
        float s1a = sm[L_CONST + 512 + c0],     o1a = sm[L_CONST + 640 + c0];
        float s1b = sm[L_CONST + 512 + c0 + 1], o1b = sm[L_CONST + 640 + c0 + 1];
        float* xr = sm + L_XP + (ln * 128 + c0) * 8;
        float* ar = sm + L_A  + (ln * 128 + c0) * 8;
        *(float4*)xr        = make_float4(v0[0], v0[1], v0[2], v0[3]);
        *(float4*)(xr + 4)  = make_float4(v0[4], v0[5], v0[6], v0[7]);
        *(float4*)(xr + 8)  = make_float4(v1[0], v1[1], v1[2], v1[3]);
        *(float4*)(xr + 12) = make_float4(v1[4], v1[5], v1[6], v1[7]);
#pragma unroll
        for (int t = 0; t < 8; t++) {
            ar[t]     = fmaxf(v0[t] * s1a + o1a, 0.f);
            ar[8 + t] = fmaxf(v1[t] * s1b + o1b, 0.f);
        }
    }
    cp_wait0();              // W1 chunk 0 arrived
    __syncthreads();         // A + WBUF visible

    // ---- conv1 (128->64) in 2 chunks of 64 c (W dup'd in WBUF) ----
    {
        int p = tid & 63;
        u64 acc1[4] = {0ULL, 0ULL, 0ULL, 0ULL};
        const ulonglong2* Abase = (const ulonglong2*)(sm + L_A + (size_t)ln * 128 * 8);
        const u64* WB = (const u64*)(sm + L_WBUF);
#pragma unroll 1
        for (int ch = 0; ch < 2; ch++) {
            if (ch == 1) {
                __syncthreads();
                stage_w<8192>(sm + L_WBUF, g_w1d + 8192, tid);
                __syncthreads();
            }
#pragma unroll 4
            for (int c2 = 0; c2 < 64; c2++) {
                int cc = ch * 64 + c2;
                u64 wd = WB[c2 * 64 + p];
                ulonglong2 u0 = Abase[cc * 2];
                ulonglong2 u1 = Abase[cc * 2 + 1];
                fma2(acc1[0], wd, u0.x);
                fma2(acc1[1], wd, u0.y);
                fma2(acc1[2], wd, u1.x);
                fma2(acc1[3], wd, u1.y);
            }
        }
        float s2 = sm[L_CONST + 64 + p], o2 = sm[L_CONST + 128 + p];
        float bb = sm[L_CONST + p];
        float* B1row = sm + L_B1 + (ln * 64 + p) * 12;
        float* B2row = sm + L_B2 + (ln * 64 + p) * 8;
        B1row[0] = 0.f; B1row[9] = 0.f;
#pragma unroll
        for (int pr = 0; pr < 4; pr++) {
            float2 v = unpack2(acc1[pr]);
            float va = fmaxf((v.x + bb) * s2 + o2, 0.f);
            float vb = fmaxf((v.y + bb) * s2 + o2, 0.f);
            B1row[1 + 2 * pr] = va;
            B1row[2 + 2 * pr] = vb;
            *(float2*)(B2row + 2 * pr) = make_float2(va, vb);
        }
    }

    // ---- conv2 (3-tap, 64->64) in 4 chunks of 16 i ----
    {
        int q = tid & 63;
        u64 acc2[4] = {0ULL, 0ULL, 0ULL, 0ULL};
        const u64* WB = (const u64*)(sm + L_WBUF);
#pragma unroll 1
        for (int chk = 0; chk < 4; chk++) {
            __syncthreads();
            stage_w<6144>(sm + L_WBUF, g_w2d + chk * 6144, tid);
            __syncthreads();
#pragma unroll 2
            for (int ii = 0; ii < 16; ii++) {
                int i = chk * 16 + ii;
                u64 W0v = WB[(ii * 3 + 0) * 64 + q];
                u64 W1v = WB[(ii * 3 + 1) * 64 + q];
                u64 W2v = WB[(ii * 3 + 2) * 64 + q];
                const float* Br = sm + L_B1 + (ln * 64 + i) * 12;
                ulonglong2 pA = *(const ulonglong2*)Br;
                ulonglong2 pB = *(const ulonglong2*)(Br + 4);
                u64 P4 = *(const u64*)(Br + 8);
                const ulonglong2* Qr = (const ulonglong2*)(sm + L_B2 + (ln * 64 + i) * 8);
                ulonglong2 qA = Qr[0], qB = Qr[1];
                u64 P[5] = {pA.x, pA.y, pB.x, pB.y, P4};
                u64 Q[4] = {qA.x, qA.y, qB.x, qB.y};
#pragma unroll
                for (int pr = 0; pr < 4; pr++) {
                    fma2(acc2[pr], W0v, P[pr]);
                    fma2(acc2[pr], W1v, Q[pr]);
                    fma2(acc2[pr], W2v, P[pr + 1]);
                }
            }
        }
        __syncthreads();
        float s3 = sm[L_CONST + 256 + q], o3v = sm[L_CONST + 320 + q];
        float bb = sm[L_CONST + 192 + q];
        float* Crow = sm + L_C + (ln * 64 + q) * 8;    // C aliases A (dead)
#pragma unroll
        for (int pr = 0; pr < 4; pr++) {
            float2 v = unpack2(acc2[pr]);
            Crow[2 * pr]     = fmaxf((v.x + bb) * s3 + o3v, 0.f);
            Crow[2 * pr + 1] = fmaxf((v.y + bb) * s3 + o3v, 0.f);
        }
    }

    // ---- conv3 (64->128) in 2 chunks of 32 q, + residual + relu + fc2 ----
    {
        int o = tid & 63;
        u64 acc3[2][4];
#pragma unroll
        for (int a = 0; a < 2; a++)
#pragma unroll
            for (int pr = 0; pr < 4; pr++) acc3[a][pr] = 0ULL;
        const u64* WB = (const u64*)(sm + L_WBUF);
#pragma unroll 1
        for (int chk = 0; chk < 2; chk++) {
            __syncthreads();
            stage_w<8192>(sm + L_WBUF, g_w3d + chk * 8192, tid);
            __syncthreads();
#pragma unroll 2
            for (int q2 = 0; q2 < 32; q2++) {
                int qq = chk * 32 + q2;
                u64 w0 = WB[q2 * 128 + o];
                u64 w1 = WB[q2 * 128 + o + 64];
                const ulonglong2* Crow =
                    (const ulonglong2*)(sm + L_C + (ln * 64 + qq) * 8);
                ulonglong2 u0 = Crow[0], u1 = Crow[1];
                fma2(acc3[0][0], w0, u0.x); fma2(acc3[0][1], w0, u0.y);
                fma2(acc3[0][2], w0, u1.x); fma2(acc3[0][3], w0, u1.y);
                fma2(acc3[1][0], w1, u0.x); fma2(acc3[1][1], w1, u0.y);
                fma2(acc3[1][2], w1, u1.x); fma2(acc3[1][3], w1, u1.y);
            }
        }
        __syncthreads();
#pragma unroll
        for (int k = 0; k < 2; k++) {
            int oo = o + 64 * k;
            float bb = sm[L_CONST + 384 + oo];
            const float* X = sm + L_XP + (ln * 128 + oo) * 8;
            const float* fw = sm + L_CONST + 768 + oo * 8;
            float lsum = 0.f;
#pragma unroll
            for (int pr = 0; pr < 4; pr++) {
                float2 v = unpack2(acc3[k][pr]);
                float v0 = fmaxf(X[2 * pr]     + v.x + bb, 0.f);
                float v1 = fmaxf(X[2 * pr + 1] + v.y + bb, 0.f);
                lsum += v0 * fw[2 * pr] + v1 * fw[2 * pr + 1];
            }
            sm[L_RED + ln * 128 + oo] = lsum;          // RED aliases B1 (dead)
        }
    }
    __syncthreads();

    // ---- reduce 128 partials per line ----
    if (tid < 128) {
        int l2 = tid >> 5, lane = tid & 31;
        float s = sm[L_RED + l2 * 128 + lane]
                + sm[L_RED + l2 * 128 + lane + 32]
                + sm[L_RED + l2 * 128 + lane + 64]
                + sm[L_RED + l2 * 128 + lane + 96];
#pragma unroll
        for (int off = 16; off > 0; off >>= 1)
            s += __shfl_xor_sync(0xffffffffu, s, off);
        if (lane == 0) out[n0 + l2] = s + fc2b[0];
    }
}

// ---------------------------------------------------------------------------
extern "C" void kernel_launch(void* const* d_in, const int* in_sizes, int n_in,
                              void* d_out, int out_size) {
    const float* feature = (const float*)d_in[0];
    const float* lines   = (const float*)d_in[1];
    const float* fc1_w   = (const float*)d_in[2];
    const float* fc1_b   = (const float*)d_in[3];
    const float* bn1g = (const float*)d_in[4];
    const float* bn1b = (const float*)d_in[5];
    const float* bn1m = (const float*)d_in[6];
    const float* bn1v = (const float*)d_in[7];
    const float* c1w  = (const float*)d_in[8];
    const float* c1b  = (const float*)d_in[9];
    const float* bn2g = (const float*)d_in[10];
    const float* bn2b = (const float*)d_in[11];
    const float* bn2m = (const float*)d_in[12];
    const float* bn2v = (const float*)d_in[13];
    const float* c2w  = (const float*)d_in[14];
    const float* c2b  = (const float*)d_in[15];
    const float* bn3g = (const float*)d_in[16];
    const float* bn3b = (const float*)d_in[17];
    const float* bn3m = (const float*)d_in[18];
    const float* bn3v = (const float*)d_in[19];
    const float* c3w  = (const float*)d_in[20];
    const float* c3b  = (const float*)d_in[21];
    const float* fc2w = (const float*)d_in[22];
    const float* fc2b = (const float*)d_in[23];
    float* out = (float*)d_out;

    cudaFuncSetAttribute(k_fc1, cudaFuncAttributeMaxDynamicSharedMemorySize,
                         FC1_SMEM_BYTES);
    cudaFuncSetAttribute(k_lines, cudaFuncAttributeMaxDynamicSharedMemorySize,
                         K2_SMEM_BYTES);

    k_prep<<<64, 256>>>(fc1_w,
                        bn1g, bn1b, bn1m, bn1v, c1w, c1b,
                        bn2g, bn2b, bn2m, bn2v, c2w, c2b,
                        bn3g, bn3b, bn3m, bn3v, c3w, c3b, fc2w);

    dim3 g1(HW * HW / 128, NB);
    k_fc1<<<g1, 256, FC1_SMEM_BYTES>>>(feature, fc1_b);

    k_lines<<<NLINES / 4, 256, K2_SMEM_BYTES>>>(lines, fc2b, out);
}

// round 9
// speedup vs baseline: 1.0218x; 1.0218x over previous
#include <cuda_runtime.h>
#include <math.h>

#define HW    128
#define CIN   256
#define DLOI  128
#define NB    8
#define NL    2048
#define NLINES (NB*NL)
#define BN_EPS 1e-5f

// Scratch: fc1 output in NHWC layout [b][i][j][o]  (64 MB)
__device__ float g_x[(size_t)NB * HW * HW * DLOI];
// Pre-transformed weights (written by k_prep each launch)
__device__ float g_w1dup[256 * 320];   // fc1 W, dup'd f32x2, conflict-free cols
__device__ float g_w1t[128 * 64];      // conv1 [c][p]
__device__ float g_w2t[192 * 64];      // conv2 [(i*3+dt)][q]
__device__ float g_w3t[64 * 128];      // conv3 [q][o]
__device__ float g_const[1792];        // biases / bn scale+offset / fc2w

// ---- packed f32x2 helpers (sm_103a dual-fp32 pipe) ----
typedef unsigned long long u64;

__device__ __forceinline__ u64 dup2(float x) {
    u64 r; asm("mov.b64 %0, {%1, %1};" : "=l"(r) : "f"(x)); return r;
}
__device__ __forceinline__ float2 unpack2(u64 v) {
    float2 f; asm("mov.b64 {%0, %1}, %2;" : "=f"(f.x), "=f"(f.y) : "l"(v)); return f;
}
__device__ __forceinline__ void fma2(u64& d, u64 a, u64 b) {
    asm("fma.rn.f32x2 %0, %1, %2, %0;" : "+l"(d) : "l"(a), "l"(b));
}
__device__ __forceinline__ void cp16(void* smem_dst, const void* gsrc) {
    unsigned s = (unsigned)__cvta_generic_to_shared(smem_dst);
    asm volatile("cp.async.ca.shared.global [%0], [%1], 16;" :: "r"(s), "l"(gsrc) : "memory");
}
__device__ __forceinline__ void cp_commit() {
    asm volatile("cp.async.commit_group;" ::: "memory");
}

// ---------------------------------------------------------------------------
// K0: weight pre-transform (runs once per launch, trivial cost)
// ---------------------------------------------------------------------------
__global__ void k_prep(const float* __restrict__ fc1w,
                       const float* __restrict__ bn1g, const float* __restrict__ bn1b,
                       const float* __restrict__ bn1m, const float* __restrict__ bn1v,
                       const float* __restrict__ c1w,  const float* __restrict__ c1b,
                       const float* __restrict__ bn2g, const float* __restrict__ bn2b,
                       const float* __restrict__ bn2m, const float* __restrict__ bn2v,
                       const float* __restrict__ c2w,  const float* __restrict__ c2b,
                       const float* __restrict__ bn3g, const float* __restrict__ bn3b,
                       const float* __restrict__ bn3m, const float* __restrict__ bn3v,
                       const float* __restrict__ c3w,  const float* __restrict__ c3b,
                       const float* __restrict__ fc2w) {
    const int tid = blockIdx.x * 256 + threadIdx.x;
    const int STR = gridDim.x * 256;
    for (int i = tid; i < 128 * 256; i += STR) {
        int o = i >> 8, k = i & 255;
        float v = fc1w[i];
        int col = (o >> 3) * 20 + (o & 7) * 2;
        g_w1dup[k * 320 + col]     = v;
        g_w1dup[k * 320 + col + 1] = v;
    }
    for (int i = tid; i < 8192; i += STR) {          // [c][p] <- c1w[p][c]
        int p = i & 63, c = i >> 6;
        g_w1t[i] = c1w[p * 128 + c];
    }
    for (int i = tid; i < 12288; i += STR) {         // [(i3)][q] <- c2w[q][i3]
        int q = i & 63, i3 = i >> 6;
        g_w2t[i] = c2w[q * 192 + i3];
    }
    for (int i = tid; i < 8192; i += STR) {          // [q][o] <- c3w[o][q]
        int o = i & 127, q = i >> 7;
        g_w3t[i] = c3w[o * 64 + q];
    }
    if (tid < 64) {
        float s2 = bn2g[tid] * rsqrtf(bn2v[tid] + BN_EPS);
        g_const[64 + tid]  = s2;
        g_const[128 + tid] = bn2b[tid] - bn2m[tid] * s2;
        g_const[tid]       = c1b[tid];
        float s3 = bn3g[tid] * rsqrtf(bn3v[tid] + BN_EPS);
        g_const[256 + tid] = s3;
        g_const[320 + tid] = bn3b[tid] - bn3m[tid] * s3;
        g_const[192 + tid] = c2b[tid];
    } else if (tid < 192) {
        int t2 = tid - 64;
        g_const[384 + t2] = c3b[t2];
        float s1 = bn1g[t2] * rsqrtf(bn1v[t2] + BN_EPS);
        g_const[512 + t2] = s1;
        g_const[640 + t2] = bn1b[t2] - bn1m[t2] * s1;
    }
    for (int i = tid; i < 1024; i += STR) g_const[768 + i] = fc2w[i];
}

// ---------------------------------------------------------------------------
// K1: fc1 SGEMM, f32x2, all staging via cp.async (W pre-dup'd by k_prep).
// Block 128pix x 128out, 256 threads, thread tile 8pix x 8out. 2 blocks/SM.
// b0 = batch offset of this chunk.
// ---------------------------------------------------------------------------
#define KT 16
#define NT (CIN / KT)
#define SA_OF(s,k) ((s)*2048 + (k)*128)
#define SW_OF(s,k) (6144 + (s)*5120 + (k)*320)
#define FC1_SMEM_FLOATS (6144 + 3*5120)
#define FC1_SMEM_BYTES  (FC1_SMEM_FLOATS * 4)

__global__ __launch_bounds__(256, 2) void k_fc1(const float* __restrict__ feat,
                                                const float* __restrict__ bias,
                                                int b0) {
    extern __shared__ float smem[];
    const int b = blockIdx.y + b0;
    const int pixbase = blockIdx.x * 128;
    const int tid = threadIdx.x;
    const int tx = tid & 15;
    const int ty = tid >> 4;

    const float* fb = feat + (size_t)b * CIN * HW * HW + pixbase;

    u64 acc[4][8];
#pragma unroll
    for (int i = 0; i < 4; i++)
#pragma unroll
        for (int j = 0; j < 8; j++) acc[i][j] = 0ULL;

#define PREF(t, s) do {                                                        \
        int i0 = tid, i1 = tid + 256;          /* A: 512 chunks of 16B */      \
        cp16(smem + SA_OF(s, i0 >> 5) + (i0 & 31) * 4,                         \
             fb + (size_t)((t)*KT + (i0 >> 5)) * (HW*HW) + (i0 & 31) * 4);     \
        cp16(smem + SA_OF(s, i1 >> 5) + (i1 & 31) * 4,                         \
             fb + (size_t)((t)*KT + (i1 >> 5)) * (HW*HW) + (i1 & 31) * 4);     \
        _Pragma("unroll")                                                      \
        for (int r = 0; r < 5; r++) {          /* W: 1280 chunks of 16B */     \
            int c = tid + r * 256;                                             \
            cp16(smem + SW_OF(s, 0) + c * 4,                                   \
                 g_w1dup + (size_t)(t) * 5120 + c * 4);                        \
        }                                                                      \
    } while (0)

    PREF(0, 0); cp_commit();
    PREF(1, 1); cp_commit();

#pragma unroll 1
    for (int t = 0; t < NT; t++) {
        if (t < NT - 1)
            asm volatile("cp.async.wait_group 1;" ::: "memory");
        else
            asm volatile("cp.async.wait_group 0;" ::: "memory");
        __syncthreads();
        if (t + 2 < NT) {
            int s = (t + 2) % 3;
            PREF(t + 2, s); cp_commit();
        }
        const int s = t % 3;
#pragma unroll
        for (int k = 0; k < KT; k++) {
            const ulonglong2* ap = (const ulonglong2*)(smem + SA_OF(s, k) + ty * 8);
            ulonglong2 a01 = ap[0], a23 = ap[1];
            const ulonglong2* wp = (const ulonglong2*)(smem + SW_OF(s, k) + tx * 20);
            ulonglong2 q0 = wp[0], q1 = wp[1], q2 = wp[2], q3 = wp[3];
            u64 av[4] = {a01.x, a01.y, a23.x, a23.y};
            u64 wd[8] = {q0.x, q0.y, q1.x, q1.y, q2.x, q2.y, q3.x, q3.y};
#pragma unroll
            for (int i = 0; i < 4; i++)
#pragma unroll
                for (int j = 0; j < 8; j++) fma2(acc[i][j], av[i], wd[j]);
        }
    }
#undef PREF

    float bv[8];
#pragma unroll
    for (int j = 0; j < 8; j++) bv[j] = bias[tx * 8 + j];
#pragma unroll
    for (int i = 0; i < 4; i++) {
        float2 vj[8];
#pragma unroll
        for (int j = 0; j < 8; j++) vj[j] = unpack2(acc[i][j]);
        size_t pix0 = (size_t)pixbase + ty * 8 + 2 * i;
        float* d0 = &g_x[((size_t)b * (HW * HW) + pix0) * DLOI + tx * 8];
        float* d1 = d0 + DLOI;
        *(float4*)d0       = make_float4(vj[0].x + bv[0], vj[1].x + bv[1],
                                         vj[2].x + bv[2], vj[3].x + bv[3]);
        *(float4*)(d0 + 4) = make_float4(vj[4].x + bv[4], vj[5].x + bv[5],
                                         vj[6].x + bv[6], vj[7].x + bv[7]);
        *(float4*)d1       = make_float4(vj[0].y + bv[0], vj[1].y + bv[1],
                                         vj[2].y + bv[2], vj[3].y + bv[3]);
        *(float4*)(d1 + 4) = make_float4(vj[4].y + bv[4], vj[5].y + bv[5],
                                         vj[6].y + bv[6], vj[7].y + bv[7]);
    }
}

// ---------------------------------------------------------------------------
// K2: fused sampling + bn1/relu + Bottleneck1D + residual + fc2.
// 4 lines per block, 256 threads, 107KB smem -> 2 blocks/SM.
// Per-phase weight staging into a single shared 12.3K-float region.
// blk0 = block offset of this chunk.
// ---------------------------------------------------------------------------
#define L_W     0        // 12288 (W1 8192 / W2 12288 / W3 8192, restaged)
#define L_XP    12288    // 4096  [ln][c][t]
#define L_A     16384    // 4096  a = relu(bn1(xp)); C aliases
#define L_C     16384
#define L_B1    20480    // 3072  [ln*64+p]*12 zero-padded; TBL/RED alias
#define L_TBL   20480
#define L_RED   20480
#define L_B2    23552    // 2048  [ln*64+p]*8 unpadded copy
#define L_CONST 25600    // 1792
#define K2_SMEM_FLOATS 27392
#define K2_SMEM_BYTES  (K2_SMEM_FLOATS * 4)

__global__ void __launch_bounds__(256, 2) k_lines(
    const float* __restrict__ lines,
    const float* __restrict__ fc2b,
    float* __restrict__ out,
    int blk0)
{
    extern __shared__ float sm[];
    const int tid = threadIdx.x;
    const int n0 = (blockIdx.x + blk0) * 4;

    // ---- phase 0: stage W1 + consts + sampling tables ----
    {
        float4* wd = (float4*)(sm + L_W);
        const float4* ws = (const float4*)g_w1t;
#pragma unroll
        for (int r = 0; r < 8; r++) wd[tid + r * 256] = ws[tid + r * 256];
        float4* cd = (float4*)(sm + L_CONST);
        const float4* cs = (const float4*)g_const;
        cd[tid] = cs[tid];
        if (tid < 192) cd[tid + 256] = cs[tid + 256];
    }
    if (tid < 128) {
        int ln = tid >> 5, p = tid & 31;
        const float* lp = lines + (size_t)(n0 + ln) * 4;
        float lam = (float)p * (1.0f / 31.0f);
        float px = lp[0] * lam + lp[2] * (1.f - lam) - 0.5f;
        float py = lp[1] * lam + lp[3] * (1.f - lam) - 0.5f;
        float px0 = fminf(fmaxf(floorf(px), 0.f), 127.f);
        float py0 = fminf(fmaxf(floorf(py), 0.f), 127.f);
        float px1 = fminf(px0 + 1.f, 127.f);
        float py1 = fminf(py0 + 1.f, 127.f);
        int ix0 = (int)px0, iy0 = (int)py0, ix1 = (int)px1, iy1 = (int)py1;
        sm[L_TBL + 0 * 128 + tid] = (px1 - px) * (py1 - py);
        sm[L_TBL + 1 * 128 + tid] = (px - px0) * (py1 - py);
        sm[L_TBL + 2 * 128 + tid] = (px1 - px) * (py - py0);
        sm[L_TBL + 3 * 128 + tid] = (px - px0) * (py - py0);
        int* ofb = (int*)(sm + L_TBL + 512);
        ofb[0 * 128 + tid] = (ix0 * HW + iy0) * (DLOI / 2);
        ofb[1 * 128 + tid] = (ix1 * HW + iy0) * (DLOI / 2);
        ofb[2 * 128 + tid] = (ix0 * HW + iy1) * (DLOI / 2);
        ofb[3 * 128 + tid] = (ix1 * HW + iy1) * (DLOI / 2);
    }
    __syncthreads();

    // ---- sampling + maxpool + fused bn1/relu ----
    {
        int ln = tid >> 6, cp = tid & 63, c0 = cp * 2;
        int bb = n0 >> 11;
        const u64* basep = (const u64*)g_x + (size_t)bb * (HW * HW) * (DLOI / 2) + cp;
        const float* wtb = sm + L_TBL;
        const int*   ofb = (const int*)(sm + L_TBL + 512);
        float v0[8], v1[8];
#pragma unroll
        for (int t = 0; t < 8; t++) {
            float m0 = -3.4e38f, m1 = -3.4e38f;
#pragma unroll
            for (int j = 0; j < 4; j++) {
                int idx = ln * 32 + t * 4 + j;
                u64 acc = 0ULL;
#pragma unroll
                for (int cn = 0; cn < 4; cn++) {
                    float wv = wtb[cn * 128 + idx];
                    u64 xv = basep[ofb[cn * 128 + idx]];
                    fma2(acc, dup2(wv), xv);
                }
                float2 s = unpack2(acc);
                m0 = fmaxf(m0, s.x);
                m1 = fmaxf(m1, s.y);
            }
            v0[t] = m0; v1[t] = m1;
        }
        float s1a = sm[L_CONST + 512 + c0],     o1a = sm[L_CONST + 640 + c0];
        float s1b = sm[L_CONST + 512 + c0 + 1], o1b = sm[L_CONST + 640 + c0 + 1];
        float* xr = sm + L_XP + (ln * 128 + c0) * 8;
        float* ar = sm + L_A  + (ln * 128 + c0) * 8;
        *(float4*)xr        = make_float4(v0[0], v0[1], v0[2], v0[3]);
        *(float4*)(xr + 4)  = make_float4(v0[4], v0[5], v0[6], v0[7]);
        *(float4*)(xr + 8)  = make_float4(v1[0], v1[1], v1[2], v1[3]);
        *(float4*)(xr + 12) = make_float4(v1[4], v1[5], v1[6], v1[7]);
#pragma unroll
        for (int t = 0; t < 8; t++) {
            ar[t]     = fmaxf(v0[t] * s1a + o1a, 0.f);
            ar[8 + t] = fmaxf(v1[t] * s1b + o1b, 0.f);
        }
    }
    __syncthreads();

    // ---- conv1 (128->64) + bias + bn2 + relu -> B1 (padded) + B2 (plain) ----
    {
        int p = tid & 63, ln = tid >> 6;
        u64 acc[4] = {0ULL, 0ULL, 0ULL, 0ULL};
        const ulonglong2* Abase = (const ulonglong2*)(sm + L_A + (size_t)ln * 128 * 8);
#pragma unroll 4
        for (int cc = 0; cc < 128; cc++) {
            u64 wd = dup2(sm[L_W + cc * 64 + p]);
            ulonglong2 u0 = Abase[cc * 2];
            ulonglong2 u1 = Abase[cc * 2 + 1];
            fma2(acc[0], wd, u0.x);
            fma2(acc[1], wd, u0.y);
            fma2(acc[2], wd, u1.x);
            fma2(acc[3], wd, u1.y);
        }
        float s2 = sm[L_CONST + 64 + p], o2 = sm[L_CONST + 128 + p];
        float bb = sm[L_CONST + p];
        float* B1row = sm + L_B1 + (ln * 64 + p) * 12;
        float* B2row = sm + L_B2 + (ln * 64 + p) * 8;
        B1row[0] = 0.f; B1row[9] = 0.f;
#pragma unroll
        for (int pr = 0; pr < 4; pr++) {
            float2 v = unpack2(acc[pr]);
            float va = fmaxf((v.x + bb) * s2 + o2, 0.f);
            float vb = fmaxf((v.y + bb) * s2 + o2, 0.f);
            B1row[1 + 2 * pr] = va;
            B1row[2 + 2 * pr] = vb;
            *(float2*)(B2row + 2 * pr) = make_float2(va, vb);
        }
    }
    __syncthreads();

    // ---- stage W2 ----
    {
        float4* wd = (float4*)(sm + L_W);
        const float4* ws = (const float4*)g_w2t;
#pragma unroll
        for (int r = 0; r < 12; r++) wd[tid + r * 256] = ws[tid + r * 256];
    }
    __syncthreads();

    // ---- conv2 (3-tap, 64->64) f32x2 + bias + bn3 + relu -> C ----
    {
        int q = tid & 63, ln = tid >> 6;
        u64 acc2[4] = {0ULL, 0ULL, 0ULL, 0ULL};
#pragma unroll 2
        for (int i = 0; i < 64; i++) {
            u64 W0 = dup2(sm[L_W + (i * 3 + 0) * 64 + q]);
            u64 W1 = dup2(sm[L_W + (i * 3 + 1) * 64 + q]);
            u64 W2 = dup2(sm[L_W + (i * 3 + 2) * 64 + q]);
            const float* Br = sm + L_B1 + (ln * 64 + i) * 12;
            ulonglong2 pA = *(const ulonglong2*)Br;
            ulonglong2 pB = *(const ulonglong2*)(Br + 4);
            u64 P4 = *(const u64*)(Br + 8);
            const ulonglong2* Qr = (const ulonglong2*)(sm + L_B2 + (ln * 64 + i) * 8);
            ulonglong2 qA = Qr[0], qB = Qr[1];
            u64 P[5] = {pA.x, pA.y, pB.x, pB.y, P4};
            u64 Q[4] = {qA.x, qA.y, qB.x, qB.y};
#pragma unroll
            for (int pr = 0; pr < 4; pr++) {
                fma2(acc2[pr], W0, P[pr]);
                fma2(acc2[pr], W1, Q[pr]);
                fma2(acc2[pr], W2, P[pr + 1]);
            }
        }
        __syncthreads();                               // all reads of B done
        float s3 = sm[L_CONST + 256 + q], o3v = sm[L_CONST + 320 + q];
        float bb = sm[L_CONST + 192 + q];
        float* Crow = sm + L_C + (ln * 64 + q) * 8;    // C aliases A (dead)
#pragma unroll
        for (int pr = 0; pr < 4; pr++) {
            float2 v = unpack2(acc2[pr]);
            Crow[2 * pr]     = fmaxf((v.x + bb) * s3 + o3v, 0.f);
            Crow[2 * pr + 1] = fmaxf((v.y + bb) * s3 + o3v, 0.f);
        }
    }
    __syncthreads();

    // ---- stage W3 ----
    {
        float4* wd = (float4*)(sm + L_W);
        const float4* ws = (const float4*)g_w3t;
#pragma unroll
        for (int r = 0; r < 8; r++) wd[tid + r * 256] = ws[tid + r * 256];
    }
    __syncthreads();

    // ---- conv3 (64->128) + residual + relu + fc2 partial ----
    {
        int o = tid & 63, ln = tid >> 6;         // handles o and o+64
        u64 acc[2][4];
#pragma unroll
        for (int a = 0; a < 2; a++)
#pragma unroll
            for (int pr = 0; pr < 4; pr++) acc[a][pr] = 0ULL;
#pragma unroll 2
        for (int q = 0; q < 64; q++) {
            u64 w0 = dup2(sm[L_W + q * 128 + o]);
            u64 w1 = dup2(sm[L_W + q * 128 + o + 64]);
            const ulonglong2* Crow = (const ulonglong2*)(sm + L_C + (ln * 64 + q) * 8);
            ulonglong2 u0 = Crow[0], u1 = Crow[1];
            fma2(acc[0][0], w0, u0.x); fma2(acc[0][1], w0, u0.y);
            fma2(acc[0][2], w0, u1.x); fma2(acc[0][3], w0, u1.y);
            fma2(acc[1][0], w1, u0.x); fma2(acc[1][1], w1, u0.y);
            fma2(acc[1][2], w1, u1.x); fma2(acc[1][3], w1, u1.y);
        }
#pragma unroll
        for (int k = 0; k < 2; k++) {
            int oo = o + 64 * k;
            float bb = sm[L_CONST + 384 + oo];
            const float* X = sm + L_XP + (ln * 128 + oo) * 8;
            const float* fw = sm + L_CONST + 768 + oo * 8;
            float lsum = 0.f;
#pragma unroll
            for (int pr = 0; pr < 4; pr++) {
                float2 v = unpack2(acc[k][pr]);
                float v0 = fmaxf(X[2 * pr]     + v.x + bb, 0.f);
                float v1 = fmaxf(X[2 * pr + 1] + v.y + bb, 0.f);
                lsum += v0 * fw[2 * pr] + v1 * fw[2 * pr + 1];
            }
            sm[L_RED + ln * 128 + oo] = lsum;          // RED aliases B1 (dead)
        }
    }
    __syncthreads();

    // ---- reduce 128 partials per line ----
    if (tid < 128) {
        int l2 = tid >> 5, lane = tid & 31;
        float s = sm[L_RED + l2 * 128 + lane]
                + sm[L_RED + l2 * 128 + lane + 32]
                + sm[L_RED + l2 * 128 + lane + 64]
                + sm[L_RED + l2 * 128 + lane + 96];
#pragma unroll
        for (int off = 16; off > 0; off >>= 1)
            s += __shfl_xor_sync(0xffffffffu, s, off);
        if (lane == 0) out[n0 + l2] = s + fc2b[0];
    }
}

// ---------------------------------------------------------------------------
// Launcher: fork/join overlap of fc1 chunks (stream 0) and line chunks
// (stream s1).  Chunk i of k_lines depends on chunk i of k_fc1 via event.
// Streams/events are created once (host resources only; the captured work is
// identical on every call).
// ---------------------------------------------------------------------------
#define NCHUNK 4

extern "C" void kernel_launch(void* const* d_in, const int* in_sizes, int n_in,
                              void* d_out, int out_size) {
    const float* feature = (const float*)d_in[0];
    const float* lines   = (const float*)d_in[1];
    const float* fc1_w   = (const float*)d_in[2];
    const float* fc1_b   = (const float*)d_in[3];
    const float* bn1g = (const float*)d_in[4];
    const float* bn1b = (const float*)d_in[5];
    const float* bn1m = (const float*)d_in[6];
    const float* bn1v = (const float*)d_in[7];
    const float* c1w  = (const float*)d_in[8];
    const float* c1b  = (const float*)d_in[9];
    const float* bn2g = (const float*)d_in[10];
    const float* bn2b = (const float*)d_in[11];
    const float* bn2m = (const float*)d_in[12];
    const float* bn2v = (const float*)d_in[13];
    const float* c2w  = (const float*)d_in[14];
    const float* c2b  = (const float*)d_in[15];
    const float* bn3g = (const float*)d_in[16];
    const float* bn3b = (const float*)d_in[17];
    const float* bn3m = (const float*)d_in[18];
    const float* bn3v = (const float*)d_in[19];
    const float* c3w  = (const float*)d_in[20];
    const float* c3b  = (const float*)d_in[21];
    const float* fc2w = (const float*)d_in[22];
    const float* fc2b = (const float*)d_in[23];
    float* out = (float*)d_out;

    static cudaStream_t s1 = nullptr;
    static cudaEvent_t evf[NCHUNK];
    static cudaEvent_t evj = nullptr;
    if (s1 == nullptr) {
        cudaStreamCreateWithFlags(&s1, cudaStreamNonBlocking);
        for (int i = 0; i < NCHUNK; i++)
            cudaEventCreateWithFlags(&evf[i], cudaEventDisableTiming);
        cudaEventCreateWithFlags(&evj, cudaEventDisableTiming);
    }

    cudaFuncSetAttribute(k_fc1, cudaFuncAttributeMaxDynamicSharedMemorySize,
                         FC1_SMEM_BYTES);
    cudaFuncSetAttribute(k_lines, cudaFuncAttributeMaxDynamicSharedMemorySize,
                         K2_SMEM_BYTES);

    k_prep<<<64, 256>>>(fc1_w,
                        bn1g, bn1b, bn1m, bn1v, c1w, c1b,
                        bn2g, bn2b, bn2m, bn2v, c2w, c2b,
                        bn3g, bn3b, bn3m, bn3v, c3w, c3b, fc2w);

    const int BPC = NB / NCHUNK;                 // batches per chunk (2)
    const int LBC = (NLINES / 4) / NCHUNK;       // line-blocks per chunk (1024)
    for (int c = 0; c < NCHUNK; c++) {
        dim3 g1(HW * HW / 128, BPC);
        k_fc1<<<g1, 256, FC1_SMEM_BYTES>>>(feature, fc1_b, c * BPC);
        cudaEventRecord(evf[c], 0);
        cudaStreamWaitEvent(s1, evf[c], 0);
        k_lines<<<LBC, 256, K2_SMEM_BYTES, s1>>>(lines, fc2b, out, c * LBC);
    }
    cudaEventRecord(evj, s1);
    cudaStreamWaitEvent(0, evj, 0);
}

// round 10
// speedup vs baseline: 1.0812x; 1.0581x over previous
#include <cuda_runtime.h>
#include <math.h>

#define HW    128
#define CIN   256
#define DLOI  128
#define NB    8
#define NL    2048
#define NLINES (NB*NL)
#define BN_EPS 1e-5f

// Scratch: fc1 output in NHWC layout [b][i][j][o]  (64 MB)
__device__ float g_x[(size_t)NB * HW * HW * DLOI];
// Pre-transformed weights (written by k_prep each launch)
__device__ float g_w1dup[256 * 320];   // fc1 W, dup'd f32x2, conflict-free cols
__device__ float g_w1t[128 * 64];      // conv1 [c][p]
__device__ float g_w2t[192 * 64];      // conv2 [(i*3+dt)][q]
__device__ float g_w3t[64 * 128];      // conv3 [q][o]
__device__ float g_const[1792];        // biases / bn scale+offset / fc2w

// ---- packed f32x2 helpers (sm_103a dual-fp32 pipe) ----
typedef unsigned long long u64;

__device__ __forceinline__ u64 dup2(float x) {
    u64 r; asm("mov.b64 %0, {%1, %1};" : "=l"(r) : "f"(x)); return r;
}
__device__ __forceinline__ float2 unpack2(u64 v) {
    float2 f; asm("mov.b64 {%0, %1}, %2;" : "=f"(f.x), "=f"(f.y) : "l"(v)); return f;
}
__device__ __forceinline__ void fma2(u64& d, u64 a, u64 b) {
    asm("fma.rn.f32x2 %0, %1, %2, %0;" : "+l"(d) : "l"(a), "l"(b));
}
__device__ __forceinline__ void cp16(void* smem_dst, const void* gsrc) {
    unsigned s = (unsigned)__cvta_generic_to_shared(smem_dst);
    asm volatile("cp.async.ca.shared.global [%0], [%1], 16;" :: "r"(s), "l"(gsrc) : "memory");
}
__device__ __forceinline__ void cp_commit() {
    asm volatile("cp.async.commit_group;" ::: "memory");
}

// ---------------------------------------------------------------------------
// K0: weight pre-transform (runs once per launch, trivial cost)
// ---------------------------------------------------------------------------
__global__ void k_prep(const float* __restrict__ fc1w,
                       const float* __restrict__ bn1g, const float* __restrict__ bn1b,
                       const float* __restrict__ bn1m, const float* __restrict__ bn1v,
                       const float* __restrict__ c1w,  const float* __restrict__ c1b,
                       const float* __restrict__ bn2g, const float* __restrict__ bn2b,
                       const float* __restrict__ bn2m, const float* __restrict__ bn2v,
                       const float* __restrict__ c2w,  const float* __restrict__ c2b,
                       const float* __restrict__ bn3g, const float* __restrict__ bn3b,
                       const float* __restrict__ bn3m, const float* __restrict__ bn3v,
                       const float* __restrict__ c3w,  const float* __restrict__ c3b,
                       const float* __restrict__ fc2w) {
    const int tid = blockIdx.x * 256 + threadIdx.x;
    const int STR = gridDim.x * 256;
    for (int i = tid; i < 128 * 256; i += STR) {
        int o = i >> 8, k = i & 255;
        float v = fc1w[i];
        int col = (o >> 3) * 20 + (o & 7) * 2;
        g_w1dup[k * 320 + col]     = v;
        g_w1dup[k * 320 + col + 1] = v;
    }
    for (int i = tid; i < 8192; i += STR) {          // [c][p] <- c1w[p][c]
        int p = i & 63, c = i >> 6;
        g_w1t[i] = c1w[p * 128 + c];
    }
    for (int i = tid; i < 12288; i += STR) {         // [(i3)][q] <- c2w[q][i3]
        int q = i & 63, i3 = i >> 6;
        g_w2t[i] = c2w[q * 192 + i3];
    }
    for (int i = tid; i < 8192; i += STR) {          // [q][o] <- c3w[o][q]
        int o = i & 127, q = i >> 7;
        g_w3t[i] = c3w[o * 64 + q];
    }
    if (tid < 64) {
        float s2 = bn2g[tid] * rsqrtf(bn2v[tid] + BN_EPS);
        g_const[64 + tid]  = s2;
        g_const[128 + tid] = bn2b[tid] - bn2m[tid] * s2;
        g_const[tid]       = c1b[tid];
        float s3 = bn3g[tid] * rsqrtf(bn3v[tid] + BN_EPS);
        g_const[256 + tid] = s3;
        g_const[320 + tid] = bn3b[tid] - bn3m[tid] * s3;
        g_const[192 + tid] = c2b[tid];
    } else if (tid < 192) {
        int t2 = tid - 64;
        g_const[384 + t2] = c3b[t2];
        float s1 = bn1g[t2] * rsqrtf(bn1v[t2] + BN_EPS);
        g_const[512 + t2] = s1;
        g_const[640 + t2] = bn1b[t2] - bn1m[t2] * s1;
    }
    for (int i = tid; i < 1024; i += STR) g_const[768 + i] = fc2w[i];
}

// ---------------------------------------------------------------------------
// K1: fc1 SGEMM, f32x2, cp.async 3-stage pipeline.
// Block tile 256pix x 128out, 512 threads, thread tile 8pix x 8out.
// W staged once per k-tile now serves 256 pixels (half the W-store traffic
// per pixel vs the 128-pix version).  110.5KB smem, 1 block/SM (16 warps).
// ---------------------------------------------------------------------------
#define KT 16
#define NT (CIN / KT)
#define PIXT 256
#define SA_OF(s,k) ((s)*4096 + (k)*256)          // 3 * 16*256
#define SW_OF(s,k) (12288 + (s)*5120 + (k)*320)  // 3 * 16*320 (dup'd)
#define FC1_SMEM_FLOATS (12288 + 3*5120)         // 27648 floats = 110.5 KB
#define FC1_SMEM_BYTES  (FC1_SMEM_FLOATS * 4)

__global__ __launch_bounds__(512, 1) void k_fc1(const float* __restrict__ feat,
                                                const float* __restrict__ bias) {
    extern __shared__ float smem[];
    const int b = blockIdx.y;
    const int pixbase = blockIdx.x * PIXT;
    const int tid = threadIdx.x;
    const int tx = tid & 15;     // o-group:  o0 = tx*8
    const int ty = tid >> 4;     // pix-group (0..31): pix0 = ty*8

    const float* fb = feat + (size_t)b * CIN * HW * HW + pixbase;

    u64 acc[4][8];
#pragma unroll
    for (int i = 0; i < 4; i++)
#pragma unroll
        for (int j = 0; j < 8; j++) acc[i][j] = 0ULL;

    // A: 4096 floats = 1024 x 16B chunks (2 per thread).  chunk c: k = c>>6,
    // pix-chunk = c&63.  W: 5120 floats = 1280 chunks (2.5 per thread).
#define PREF(t, s) do {                                                        \
        int c0 = tid, c1 = tid + 512;                                          \
        cp16(smem + SA_OF(s, c0 >> 6) + (c0 & 63) * 4,                         \
             fb + (size_t)((t)*KT + (c0 >> 6)) * (HW*HW) + (c0 & 63) * 4);     \
        cp16(smem + SA_OF(s, c1 >> 6) + (c1 & 63) * 4,                         \
             fb + (size_t)((t)*KT + (c1 >> 6)) * (HW*HW) + (c1 & 63) * 4);     \
        cp16(smem + SW_OF(s, 0) + tid * 4,                                     \
             g_w1dup + (size_t)(t) * 5120 + tid * 4);                          \
        cp16(smem + SW_OF(s, 0) + (tid + 512) * 4,                             \
             g_w1dup + (size_t)(t) * 5120 + (tid + 512) * 4);                  \
        if (tid < 256)                                                         \
            cp16(smem + SW_OF(s, 0) + (tid + 1024) * 4,                        \
                 g_w1dup + (size_t)(t) * 5120 + (tid + 1024) * 4);             \
    } while (0)

    PREF(0, 0); cp_commit();
    PREF(1, 1); cp_commit();

#pragma unroll 1
    for (int t = 0; t < NT; t++) {
        if (t < NT - 1)
            asm volatile("cp.async.wait_group 1;" ::: "memory");
        else
            asm volatile("cp.async.wait_group 0;" ::: "memory");
        __syncthreads();
        if (t + 2 < NT) {
            int s = (t + 2) % 3;
            PREF(t + 2, s); cp_commit();
        }
        const int s = t % 3;
#pragma unroll
        for (int k = 0; k < KT; k++) {
            const ulonglong2* ap = (const ulonglong2*)(smem + SA_OF(s, k) + ty * 8);
            ulonglong2 a01 = ap[0], a23 = ap[1];
            const ulonglong2* wp = (const ulonglong2*)(smem + SW_OF(s, k) + tx * 20);
            ulonglong2 q0 = wp[0], q1 = wp[1], q2 = wp[2], q3 = wp[3];
            u64 av[4] = {a01.x, a01.y, a23.x, a23.y};
            u64 wd[8] = {q0.x, q0.y, q1.x, q1.y, q2.x, q2.y, q3.x, q3.y};
#pragma unroll
            for (int i = 0; i < 4; i++)
#pragma unroll
                for (int j = 0; j < 8; j++) fma2(acc[i][j], av[i], wd[j]);
        }
        // no trailing barrier: iteration t+1's leading __syncthreads orders
        // compute(t) before any PREF into this stage.
    }
#undef PREF

    float bv[8];
#pragma unroll
    for (int j = 0; j < 8; j++) bv[j] = bias[tx * 8 + j];
#pragma unroll
    for (int i = 0; i < 4; i++) {
        float2 vj[8];
#pragma unroll
        for (int j = 0; j < 8; j++) vj[j] = unpack2(acc[i][j]);
        size_t pix0 = (size_t)pixbase + ty * 8 + 2 * i;
        float* d0 = &g_x[((size_t)b * (HW * HW) + pix0) * DLOI + tx * 8];
        float* d1 = d0 + DLOI;
        *(float4*)d0       = make_float4(vj[0].x + bv[0], vj[1].x + bv[1],
                                         vj[2].x + bv[2], vj[3].x + bv[3]);
        *(float4*)(d0 + 4) = make_float4(vj[4].x + bv[4], vj[5].x + bv[5],
                                         vj[6].x + bv[6], vj[7].x + bv[7]);
        *(float4*)d1       = make_float4(vj[0].y + bv[0], vj[1].y + bv[1],
                                         vj[2].y + bv[2], vj[3].y + bv[3]);
        *(float4*)(d1 + 4) = make_float4(vj[4].y + bv[4], vj[5].y + bv[5],
                                         vj[6].y + bv[6], vj[7].y + bv[7]);
    }
}

// ---------------------------------------------------------------------------
// K2: fused sampling + bn1/relu + Bottleneck1D + residual + fc2.
// 4 lines per block, 256 threads, 107KB smem -> 2 blocks/SM.  (exact R5)
// ---------------------------------------------------------------------------
#define L_W     0        // 12288 (W1 8192 / W2 12288 / W3 8192, restaged)
#define L_XP    12288    // 4096  [ln][c][t]
#define L_A     16384    // 4096  a = relu(bn1(xp)); C aliases
#define L_C     16384
#define L_B1    20480    // 3072  [ln*64+p]*12 zero-padded; TBL/RED alias
#define L_TBL   20480
#define L_RED   20480
#define L_B2    23552    // 2048  [ln*64+p]*8 unpadded copy
#define L_CONST 25600    // 1792
#define K2_SMEM_FLOATS 27392
#define K2_SMEM_BYTES  (K2_SMEM_FLOATS * 4)

__global__ void __launch_bounds__(256, 2) k_lines(
    const float* __restrict__ lines,
    const float* __restrict__ fc2b,
    float* __restrict__ out)
{
    extern __shared__ float sm[];
    const int tid = threadIdx.x;
    const int n0 = blockIdx.x * 4;

    // ---- phase 0: stage W1 + consts + sampling tables ----
    {
        float4* wd = (float4*)(sm + L_W);
        const float4* ws = (const float4*)g_w1t;
#pragma unroll
        for (int r = 0; r < 8; r++) wd[tid + r * 256] = ws[tid + r * 256];
        float4* cd = (float4*)(sm + L_CONST);
        const float4* cs = (const float4*)g_const;
        cd[tid] = cs[tid];
        if (tid < 192) cd[tid + 256] = cs[tid + 256];
    }
    if (tid < 128) {
        int ln = tid >> 5, p = tid & 31;
        const float* lp = lines + (size_t)(n0 + ln) * 4;
        float lam = (float)p * (1.0f / 31.0f);
        float px = lp[0] * lam + lp[2] * (1.f - lam) - 0.5f;
        float py = lp[1] * lam + lp[3] * (1.f - lam) - 0.5f;
        float px0 = fminf(fmaxf(floorf(px), 0.f), 127.f);
        float py0 = fminf(fmaxf(floorf(py), 0.f), 127.f);
        float px1 = fminf(px0 + 1.f, 127.f);
        float py1 = fminf(py0 + 1.f, 127.f);
        int ix0 = (int)px0, iy0 = (int)py0, ix1 = (int)px1, iy1 = (int)py1;
        sm[L_TBL + 0 * 128 + tid] = (px1 - px) * (py1 - py);
        sm[L_TBL + 1 * 128 + tid] = (px - px0) * (py1 - py);
        sm[L_TBL + 2 * 128 + tid] = (px1 - px) * (py - py0);
        sm[L_TBL + 3 * 128 + tid] = (px - px0) * (py - py0);
        int* ofb = (int*)(sm + L_TBL + 512);
        ofb[0 * 128 + tid] = (ix0 * HW + iy0) * (DLOI / 2);
        ofb[1 * 128 + tid] = (ix1 * HW + iy0) * (DLOI / 2);
        ofb[2 * 128 + tid] = (ix0 * HW + iy1) * (DLOI / 2);
        ofb[3 * 128 + tid] = (ix1 * HW + iy1) * (DLOI / 2);
    }
    __syncthreads();

    // ---- sampling + maxpool + fused bn1/relu ----
    {
        int ln = tid >> 6, cp = tid & 63, c0 = cp * 2;
        int bb = n0 >> 11;
        const u64* basep = (const u64*)g_x + (size_t)bb * (HW * HW) * (DLOI / 2) + cp;
        const float* wtb = sm + L_TBL;
        const int*   ofb = (const int*)(sm + L_TBL + 512);
        float v0[8], v1[8];
#pragma unroll
        for (int t = 0; t < 8; t++) {
            float m0 = -3.4e38f, m1 = -3.4e38f;
#pragma unroll
            for (int j = 0; j < 4; j++) {
                int idx = ln * 32 + t * 4 + j;
                u64 acc = 0ULL;
#pragma unroll
                for (int cn = 0; cn < 4; cn++) {
                    float wv = wtb[cn * 128 + idx];
                    u64 xv = basep[ofb[cn * 128 + idx]];
                    fma2(acc, dup2(wv), xv);
                }
                float2 s = unpack2(acc);
                m0 = fmaxf(m0, s.x);
                m1 = fmaxf(m1, s.y);
            }
            v0[t] = m0; v1[t] = m1;
        }
        float s1a = sm[L_CONST + 512 + c0],     o1a = sm[L_CONST + 640 + c0];
        float s1b = sm[L_CONST + 512 + c0 + 1], o1b = sm[L_CONST + 640 + c0 + 1];
        float* xr = sm + L_XP + (ln * 128 + c0) * 8;
        float* ar = sm + L_A  + (ln * 128 + c0) * 8;
        *(float4*)xr        = make_float4(v0[0], v0[1], v0[2], v0[3]);
        *(float4*)(xr + 4)  = make_float4(v0[4], v0[5], v0[6], v0[7]);
        *(float4*)(xr + 8)  = make_float4(v1[0], v1[1], v1[2], v1[3]);
        *(float4*)(xr + 12) = make_float4(v1[4], v1[5], v1[6], v1[7]);
#pragma unroll
        for (int t = 0; t < 8; t++) {
            ar[t]     = fmaxf(v0[t] * s1a + o1a, 0.f);
            ar[8 + t] = fmaxf(v1[t] * s1b + o1b, 0.f);
        }
    }
    __syncthreads();

    // ---- conv1 (128->64) + bias + bn2 + relu -> B1 (padded) + B2 (plain) ----
    {
        int p = tid & 63, ln = tid >> 6;
        u64 acc[4] = {0ULL, 0ULL, 0ULL, 0ULL};
        const ulonglong2* Abase = (const ulonglong2*)(sm + L_A + (size_t)ln * 128 * 8);
#pragma unroll 4
        for (int cc = 0; cc < 128; cc++) {
            u64 wd = dup2(sm[L_W + cc * 64 + p]);
            ulonglong2 u0 = Abase[cc * 2];
            ulonglong2 u1 = Abase[cc * 2 + 1];
            fma2(acc[0], wd, u0.x);
            fma2(acc[1], wd, u0.y);
            fma2(acc[2], wd, u1.x);
            fma2(acc[3], wd, u1.y);
        }
        float s2 = sm[L_CONST + 64 + p], o2 = sm[L_CONST + 128 + p];
        float bb = sm[L_CONST + p];
        float* B1row = sm + L_B1 + (ln * 64 + p) * 12;
        float* B2row = sm + L_B2 + (ln * 64 + p) * 8;
        B1row[0] = 0.f; B1row[9] = 0.f;
#pragma unroll
        for (int pr = 0; pr < 4; pr++) {
            float2 v = unpack2(acc[pr]);
            float va = fmaxf((v.x + bb) * s2 + o2, 0.f);
            float vb = fmaxf((v.y + bb) * s2 + o2, 0.f);
            B1row[1 + 2 * pr] = va;
            B1row[2 + 2 * pr] = vb;
            *(float2*)(B2row + 2 * pr) = make_float2(va, vb);
        }
    }
    __syncthreads();

    // ---- stage W2 ----
    {
        float4* wd = (float4*)(sm + L_W);
        const float4* ws = (const float4*)g_w2t;
#pragma unroll
        for (int r = 0; r < 12; r++) wd[tid + r * 256] = ws[tid + r * 256];
    }
    __syncthreads();

    // ---- conv2 (3-tap, 64->64) f32x2 + bias + bn3 + relu -> C ----
    {
        int q = tid & 63, ln = tid >> 6;
        u64 acc2[4] = {0ULL, 0ULL, 0ULL, 0ULL};
#pragma unroll 2
        for (int i = 0; i < 64; i++) {
            u64 W0 = dup2(sm[L_W + (i * 3 + 0) * 64 + q]);
            u64 W1 = dup2(sm[L_W + (i * 3 + 1) * 64 + q]);
            u64 W2 = dup2(sm[L_W + (i * 3 + 2) * 64 + q]);
            const float* Br = sm + L_B1 + (ln * 64 + i) * 12;
            ulonglong2 pA = *(const ulonglong2*)Br;
            ulonglong2 pB = *(const ulonglong2*)(Br + 4);
            u64 P4 = *(const u64*)(Br + 8);
            const ulonglong2* Qr = (const ulonglong2*)(sm + L_B2 + (ln * 64 + i) * 8);
            ulonglong2 qA = Qr[0], qB = Qr[1];
            u64 P[5] = {pA.x, pA.y, pB.x, pB.y, P4};
            u64 Q[4] = {qA.x, qA.y, qB.x, qB.y};
#pragma unroll
            for (int pr = 0; pr < 4; pr++) {
                fma2(acc2[pr], W0, P[pr]);
                fma2(acc2[pr], W1, Q[pr]);
                fma2(acc2[pr], W2, P[pr + 1]);
            }
        }
        __syncthreads();                               // all reads of B done
        float s3 = sm[L_CONST + 256 + q], o3v = sm[L_CONST + 320 + q];
        float bb = sm[L_CONST + 192 + q];
        float* Crow = sm + L_C + (ln * 64 + q) * 8;    // C aliases A (dead)
#pragma unroll
        for (int pr = 0; pr < 4; pr++) {
            float2 v = unpack2(acc2[pr]);
            Crow[2 * pr]     = fmaxf((v.x + bb) * s3 + o3v, 0.f);
            Crow[2 * pr + 1] = fmaxf((v.y + bb) * s3 + o3v, 0.f);
        }
    }
    __syncthreads();

    // ---- stage W3 ----
    {
        float4* wd = (float4*)(sm + L_W);
        const float4* ws = (const float4*)g_w3t;
#pragma unroll
        for (int r = 0; r < 8; r++) wd[tid + r * 256] = ws[tid + r * 256];
    }
    __syncthreads();

    // ---- conv3 (64->128) + residual + relu + fc2 partial ----
    {
        int o = tid & 63, ln = tid >> 6;         // handles o and o+64
        u64 acc[2][4];
#pragma unroll
        for (int a = 0; a < 2; a++)
#pragma unroll
            for (int pr = 0; pr < 4; pr++) acc[a][pr] = 0ULL;
#pragma unroll 2
        for (int q = 0; q < 64; q++) {
            u64 w0 = dup2(sm[L_W + q * 128 + o]);
            u64 w1 = dup2(sm[L_W + q * 128 + o + 64]);
            const ulonglong2* Crow = (const ulonglong2*)(sm + L_C + (ln * 64 + q) * 8);
            ulonglong2 u0 = Crow[0], u1 = Crow[1];
            fma2(acc[0][0], w0, u0.x); fma2(acc[0][1], w0, u0.y);
            fma2(acc[0][2], w0, u1.x); fma2(acc[0][3], w0, u1.y);
            fma2(acc[1][0], w1, u0.x); fma2(acc[1][1], w1, u0.y);
            fma2(acc[1][2], w1, u1.x); fma2(acc[1][3], w1, u1.y);
        }
#pragma unroll
        for (int k = 0; k < 2; k++) {
            int oo = o + 64 * k;
            float bb = sm[L_CONST + 384 + oo];
            const float* X = sm + L_XP + (ln * 128 + oo) * 8;
            const float* fw = sm + L_CONST + 768 + oo * 8;
            float lsum = 0.f;
#pragma unroll
            for (int pr = 0; pr < 4; pr++) {
                float2 v = unpack2(acc[k][pr]);
                float v0 = fmaxf(X[2 * pr]     + v.x + bb, 0.f);
                float v1 = fmaxf(X[2 * pr + 1] + v.y + bb, 0.f);
                lsum += v0 * fw[2 * pr] + v1 * fw[2 * pr + 1];
            }
            sm[L_RED + ln * 128 + oo] = lsum;          // RED aliases B1 (dead)
        }
    }
    __syncthreads();

    // ---- reduce 128 partials per line ----
    if (tid < 128) {
        int l2 = tid >> 5, lane = tid & 31;
        float s = sm[L_RED + l2 * 128 + lane]
                + sm[L_RED + l2 * 128 + lane + 32]
                + sm[L_RED + l2 * 128 + lane + 64]
                + sm[L_RED + l2 * 128 + lane + 96];
#pragma unroll
        for (int off = 16; off > 0; off >>= 1)
            s += __shfl_xor_sync(0xffffffffu, s, off);
        if (lane == 0) out[n0 + l2] = s + fc2b[0];
    }
}

// ---------------------------------------------------------------------------
extern "C" void kernel_launch(void* const* d_in, const int* in_sizes, int n_in,
                              void* d_out, int out_size) {
    const float* feature = (const float*)d_in[0];
    const float* lines   = (const float*)d_in[1];
    const float* fc1_w   = (const float*)d_in[2];
    const float* fc1_b   = (const float*)d_in[3];
    const float* bn1g = (const float*)d_in[4];
    const float* bn1b = (const float*)d_in[5];
    const float* bn1m = (const float*)d_in[6];
    const float* bn1v = (const float*)d_in[7];
    const float* c1w  = (const float*)d_in[8];
    const float* c1b  = (const float*)d_in[9];
    const float* bn2g = (const float*)d_in[10];
    const float* bn2b = (const float*)d_in[11];
    const float* bn2m = (const float*)d_in[12];
    const float* bn2v = (const float*)d_in[13];
    const float* c2w  = (const float*)d_in[14];
    const float* c2b  = (const float*)d_in[15];
    const float* bn3g = (const float*)d_in[16];
    const float* bn3b = (const float*)d_in[17];
    const float* bn3m = (const float*)d_in[18];
    const float* bn3v = (const float*)d_in[19];
    const float* c3w  = (const float*)d_in[20];
    const float* c3b  = (const float*)d_in[21];
    const float* fc2w = (const float*)d_in[22];
    const float* fc2b = (const float*)d_in[23];
    float* out = (float*)d_out;

    cudaFuncSetAttribute(k_fc1, cudaFuncAttributeMaxDynamicSharedMemorySize,
                         FC1_SMEM_BYTES);
    cudaFuncSetAttribute(k_lines, cudaFuncAttributeMaxDynamicSharedMemorySize,
                         K2_SMEM_BYTES);

    k_prep<<<64, 256>>>(fc1_w,
                        bn1g, bn1b, bn1m, bn1v, c1w, c1b,
                        bn2g, bn2b, bn2m, bn2v, c2w, c2b,
                        bn3g, bn3b, bn3m, bn3v, c3w, c3b, fc2w);

    dim3 g1(HW * HW / PIXT, NB);
    k_fc1<<<g1, 512, FC1_SMEM_BYTES>>>(feature, fc1_b);

    k_lines<<<NLINES / 4, 256, K2_SMEM_BYTES>>>(lines, fc2b, out);
}

// round 11
// speedup vs baseline: 1.2184x; 1.1269x over previous
#include <cuda_runtime.h>
#include <math.h>

#define HW    128
#define CIN   256
#define DLOI  128
#define NB    8
#define NL    2048
#define NLINES (NB*NL)
#define BN_EPS 1e-5f

// Scratch: fc1 output in NHWC layout [b][i][j][o]  (64 MB)
__device__ float g_x[(size_t)NB * HW * HW * DLOI];
// Pre-transformed weights (written by k_prep each launch)
__device__ float g_w1p[256 * 128];     // fc1 W transposed [k][o] (plain)
__device__ float g_w1t[128 * 64];      // conv1 [c][p]
__device__ float g_w2t[192 * 64];      // conv2 [(i*3+dt)][q]
__device__ float g_w3t[64 * 128];      // conv3 [q][o]
__device__ float g_const[1792];        // biases / bn scale+offset / fc2w

// ---- packed f32x2 helpers (sm_103a dual-fp32 pipe) ----
typedef unsigned long long u64;

__device__ __forceinline__ u64 dup2(float x) {
    u64 r; asm("mov.b64 %0, {%1, %1};" : "=l"(r) : "f"(x)); return r;
}
__device__ __forceinline__ float2 unpack2(u64 v) {
    float2 f; asm("mov.b64 {%0, %1}, %2;" : "=f"(f.x), "=f"(f.y) : "l"(v)); return f;
}
__device__ __forceinline__ void fma2(u64& d, u64 a, u64 b) {
    asm("fma.rn.f32x2 %0, %1, %2, %0;" : "+l"(d) : "l"(a), "l"(b));
}
__device__ __forceinline__ void cp16(void* smem_dst, const void* gsrc) {
    unsigned s = (unsigned)__cvta_generic_to_shared(smem_dst);
    asm volatile("cp.async.ca.shared.global [%0], [%1], 16;" :: "r"(s), "l"(gsrc) : "memory");
}
__device__ __forceinline__ void cp_commit() {
    asm volatile("cp.async.commit_group;" ::: "memory");
}

// ---------------------------------------------------------------------------
// K0: weight pre-transform (runs once per launch, trivial cost)
// ---------------------------------------------------------------------------
__global__ void k_prep(const float* __restrict__ fc1w,
                       const float* __restrict__ bn1g, const float* __restrict__ bn1b,
                       const float* __restrict__ bn1m, const float* __restrict__ bn1v,
                       const float* __restrict__ c1w,  const float* __restrict__ c1b,
                       const float* __restrict__ bn2g, const float* __restrict__ bn2b,
                       const float* __restrict__ bn2m, const float* __restrict__ bn2v,
                       const float* __restrict__ c2w,  const float* __restrict__ c2b,
                       const float* __restrict__ bn3g, const float* __restrict__ bn3b,
                       const float* __restrict__ bn3m, const float* __restrict__ bn3v,
                       const float* __restrict__ c3w,  const float* __restrict__ c3b,
                       const float* __restrict__ fc2w) {
    const int tid = blockIdx.x * 256 + threadIdx.x;
    const int STR = gridDim.x * 256;
    for (int i = tid; i < 128 * 256; i += STR) {     // [k][o] <- fc1w[o][k]
        int o = i >> 8, k = i & 255;
        g_w1p[k * 128 + o] = fc1w[i];
    }
    for (int i = tid; i < 8192; i += STR) {          // [c][p] <- c1w[p][c]
        int p = i & 63, c = i >> 6;
        g_w1t[i] = c1w[p * 128 + c];
    }
    for (int i = tid; i < 12288; i += STR) {         // [(i3)][q] <- c2w[q][i3]
        int q = i & 63, i3 = i >> 6;
        g_w2t[i] = c2w[q * 192 + i3];
    }
    for (int i = tid; i < 8192; i += STR) {          // [q][o] <- c3w[o][q]
        int o = i & 127, q = i >> 7;
        g_w3t[i] = c3w[o * 64 + q];
    }
    if (tid < 64) {
        float s2 = bn2g[tid] * rsqrtf(bn2v[tid] + BN_EPS);
        g_const[64 + tid]  = s2;
        g_const[128 + tid] = bn2b[tid] - bn2m[tid] * s2;
        g_const[tid]       = c1b[tid];
        float s3 = bn3g[tid] * rsqrtf(bn3v[tid] + BN_EPS);
        g_const[256 + tid] = s3;
        g_const[320 + tid] = bn3b[tid] - bn3m[tid] * s3;
        g_const[192 + tid] = c2b[tid];
    } else if (tid < 192) {
        int t2 = tid - 64;
        g_const[384 + t2] = c3b[t2];
        float s1 = bn1g[t2] * rsqrtf(bn1v[t2] + BN_EPS);
        g_const[512 + t2] = s1;
        g_const[640 + t2] = bn1b[t2] - bn1m[t2] * s1;
    }
    for (int i = tid; i < 1024; i += STR) g_const[768 + i] = fc2w[i];
}

// ---------------------------------------------------------------------------
// K1: fc1 SGEMM, f32x2, cp.async 3-stage pipeline.
// Block 128pix x 128out, 256 threads = 8 warps.
// Warp w -> outputs [w*16, w*16+16); lane -> pixels [lane*4, lane*4+4).
// W reads are broadcast LDS.128 (plain [k][o] layout, dup in-register on the
// ALU pipe); A reads are 512B contiguous per warp.  2 blocks/SM.
// ---------------------------------------------------------------------------
#define KT 16
#define NT (CIN / KT)
#define SA_OF(s,k) ((s)*2048 + (k)*128)          // 3 * 2048
#define SW_OF(s,k) (6144 + (s)*2048 + (k)*128)   // 3 * 2048 (plain [k][o])
#define FC1_SMEM_FLOATS 12288                    // 48 KB
#define FC1_SMEM_BYTES  (FC1_SMEM_FLOATS * 4)

__global__ __launch_bounds__(256, 2) void k_fc1(const float* __restrict__ feat,
                                                const float* __restrict__ bias) {
    extern __shared__ float smem[];
    const int b = blockIdx.y;
    const int pixbase = blockIdx.x * 128;
    const int tid = threadIdx.x;
    const int w = tid >> 5;       // warp -> o0 = w*16
    const int lane = tid & 31;    // lane -> pix0 = lane*4

    const float* fb = feat + (size_t)b * CIN * HW * HW + pixbase;

    u64 acc[2][16];               // [pix-pair][o]
#pragma unroll
    for (int i = 0; i < 2; i++)
#pragma unroll
        for (int j = 0; j < 16; j++) acc[i][j] = 0ULL;

    // A: 2048 floats = 512 chunks (2/thread).  W: 2048 floats = 512 (2/thread).
#define PREF(t, s) do {                                                        \
        int c0 = tid, c1 = tid + 256;                                          \
        cp16(smem + SA_OF(s, c0 >> 5) + (c0 & 31) * 4,                         \
             fb + (size_t)((t)*KT + (c0 >> 5)) * (HW*HW) + (c0 & 31) * 4);     \
        cp16(smem + SA_OF(s, c1 >> 5) + (c1 & 31) * 4,                         \
             fb + (size_t)((t)*KT + (c1 >> 5)) * (HW*HW) + (c1 & 31) * 4);     \
        cp16(smem + SW_OF(s, c0 >> 5) + (c0 & 31) * 4,                         \
             g_w1p + (size_t)((t)*KT + (c0 >> 5)) * 128 + (c0 & 31) * 4);      \
        cp16(smem + SW_OF(s, c1 >> 5) + (c1 & 31) * 4,                         \
             g_w1p + (size_t)((t)*KT + (c1 >> 5)) * 128 + (c1 & 31) * 4);      \
    } while (0)

    PREF(0, 0); cp_commit();
    PREF(1, 1); cp_commit();

#pragma unroll 1
    for (int t = 0; t < NT; t++) {
        if (t < NT - 1)
            asm volatile("cp.async.wait_group 1;" ::: "memory");
        else
            asm volatile("cp.async.wait_group 0;" ::: "memory");
        __syncthreads();
        if (t + 2 < NT) {
            int s = (t + 2) % 3;
            PREF(t + 2, s); cp_commit();
        }
        const int s = t % 3;
#pragma unroll
        for (int k = 0; k < KT; k++) {
            ulonglong2 av2 = *(const ulonglong2*)(smem + SA_OF(s, k) + lane * 4);
            u64 a0 = av2.x, a1 = av2.y;
            const float4* wr = (const float4*)(smem + SW_OF(s, k) + w * 16);
            float4 w0 = wr[0], w1 = wr[1], w2 = wr[2], w3 = wr[3];
            float wf[16] = {w0.x, w0.y, w0.z, w0.w, w1.x, w1.y, w1.z, w1.w,
                            w2.x, w2.y, w2.z, w2.w, w3.x, w3.y, w3.z, w3.w};
#pragma unroll
            for (int j = 0; j < 16; j++) {
                u64 wd = dup2(wf[j]);
                fma2(acc[0][j], a0, wd);
                fma2(acc[1][j], a1, wd);
            }
        }
    }
#undef PREF

    float bv[16];
#pragma unroll
    for (int j = 0; j < 16; j++) bv[j] = bias[w * 16 + j];
#pragma unroll
    for (int i = 0; i < 2; i++) {
        float2 vj[16];
#pragma unroll
        for (int j = 0; j < 16; j++) vj[j] = unpack2(acc[i][j]);
        size_t pix0 = (size_t)pixbase + lane * 4 + 2 * i;
        float* d0 = &g_x[((size_t)b * (HW * HW) + pix0) * DLOI + w * 16];
        float* d1 = d0 + DLOI;
#pragma unroll
        for (int r = 0; r < 4; r++) {
            *(float4*)(d0 + r * 4) = make_float4(
                vj[r * 4 + 0].x + bv[r * 4 + 0], vj[r * 4 + 1].x + bv[r * 4 + 1],
                vj[r * 4 + 2].x + bv[r * 4 + 2], vj[r * 4 + 3].x + bv[r * 4 + 3]);
            *(float4*)(d1 + r * 4) = make_float4(
                vj[r * 4 + 0].y + bv[r * 4 + 0], vj[r * 4 + 1].y + bv[r * 4 + 1],
                vj[r * 4 + 2].y + bv[r * 4 + 2], vj[r * 4 + 3].y + bv[r * 4 + 3]);
        }
    }
}

// ---------------------------------------------------------------------------
// K2: fused sampling + bn1/relu + Bottleneck1D + residual + fc2.
// 4 lines per block, 256 threads, 107KB smem -> 2 blocks/SM.  (exact R5)
// ---------------------------------------------------------------------------
#define L_W     0        // 12288 (W1 8192 / W2 12288 / W3 8192, restaged)
#define L_XP    12288    // 4096  [ln][c][t]
#define L_A     16384    // 4096  a = relu(bn1(xp)); C aliases
#define L_C     16384
#define L_B1    20480    // 3072  [ln*64+p]*12 zero-padded; TBL/RED alias
#define L_TBL   20480
#define L_RED   20480
#define L_B2    23552    // 2048  [ln*64+p]*8 unpadded copy
#define L_CONST 25600    // 1792
#define K2_SMEM_FLOATS 27392
#define K2_SMEM_BYTES  (K2_SMEM_FLOATS * 4)

__global__ void __launch_bounds__(256, 2) k_lines(
    const float* __restrict__ lines,
    const float* __restrict__ fc2b,
    float* __restrict__ out)
{
    extern __shared__ float sm[];
    const int tid = threadIdx.x;
    const int n0 = blockIdx.x * 4;

    // ---- phase 0: stage W1 + consts + sampling tables ----
    {
        float4* wd = (float4*)(sm + L_W);
        const float4* ws = (const float4*)g_w1t;
#pragma unroll
        for (int r = 0; r < 8; r++) wd[tid + r * 256] = ws[tid + r * 256];
        float4* cd = (float4*)(sm + L_CONST);
        const float4* cs = (const float4*)g_const;
        cd[tid] = cs[tid];
        if (tid < 192) cd[tid + 256] = cs[tid + 256];
    }
    if (tid < 128) {
        int ln = tid >> 5, p = tid & 31;
        const float* lp = lines + (size_t)(n0 + ln) * 4;
        float lam = (float)p * (1.0f / 31.0f);
        float px = lp[0] * lam + lp[2] * (1.f - lam) - 0.5f;
        float py = lp[1] * lam + lp[3] * (1.f - lam) - 0.5f;
        float px0 = fminf(fmaxf(floorf(px), 0.f), 127.f);
        float py0 = fminf(fmaxf(floorf(py), 0.f), 127.f);
        float px1 = fminf(px0 + 1.f, 127.f);
        float py1 = fminf(py0 + 1.f, 127.f);
        int ix0 = (int)px0, iy0 = (int)py0, ix1 = (int)px1, iy1 = (int)py1;
        sm[L_TBL + 0 * 128 + tid] = (px1 - px) * (py1 - py);
        sm[L_TBL + 1 * 128 + tid] = (px - px0) * (py1 - py);
        sm[L_TBL + 2 * 128 + tid] = (px1 - px) * (py - py0);
        sm[L_TBL + 3 * 128 + tid] = (px - px0) * (py - py0);
        int* ofb = (int*)(sm + L_TBL + 512);
        ofb[0 * 128 + tid] = (ix0 * HW + iy0) * (DLOI / 2);
        ofb[1 * 128 + tid] = (ix1 * HW + iy0) * (DLOI / 2);
        ofb[2 * 128 + tid] = (ix0 * HW + iy1) * (DLOI / 2);
        ofb[3 * 128 + tid] = (ix1 * HW + iy1) * (DLOI / 2);
    }
    __syncthreads();

    // ---- sampling + maxpool + fused bn1/relu ----
    {
        int ln = tid >> 6, cp = tid & 63, c0 = cp * 2;
        int bb = n0 >> 11;
        const u64* basep = (const u64*)g_x + (size_t)bb * (HW * HW) * (DLOI / 2) + cp;
        const float* wtb = sm + L_TBL;
        const int*   ofb = (const int*)(sm + L_TBL + 512);
        float v0[8], v1[8];
#pragma unroll
        for (int t = 0; t < 8; t++) {
            float m0 = -3.4e38f, m1 = -3.4e38f;
#pragma unroll
            for (int j = 0; j < 4; j++) {
                int idx = ln * 32 + t * 4 + j;
                u64 acc = 0ULL;
#pragma unroll
                for (int cn = 0; cn < 4; cn++) {
                    float wv = wtb[cn * 128 + idx];
                    u64 xv = basep[ofb[cn * 128 + idx]];
                    fma2(acc, dup2(wv), xv);
                }
                float2 s = unpack2(acc);
                m0 = fmaxf(m0, s.x);
                m1 = fmaxf(m1, s.y);
            }
            v0[t] = m0; v1[t] = m1;
        }
        float s1a = sm[L_CONST + 512 + c0],     o1a = sm[L_CONST + 640 + c0];
        float s1b = sm[L_CONST + 512 + c0 + 1], o1b = sm[L_CONST + 640 + c0 + 1];
        float* xr = sm + L_XP + (ln * 128 + c0) * 8;
        float* ar = sm + L_A  + (ln * 128 + c0) * 8;
        *(float4*)xr        = make_float4(v0[0], v0[1], v0[2], v0[3]);
        *(float4*)(xr + 4)  = make_float4(v0[4], v0[5], v0[6], v0[7]);
        *(float4*)(xr + 8)  = make_float4(v1[0], v1[1], v1[2], v1[3]);
        *(float4*)(xr + 12) = make_float4(v1[4], v1[5], v1[6], v1[7]);
#pragma unroll
        for (int t = 0; t < 8; t++) {
            ar[t]     = fmaxf(v0[t] * s1a + o1a, 0.f);
            ar[8 + t] = fmaxf(v1[t] * s1b + o1b, 0.f);
        }
    }
    __syncthreads();

    // ---- conv1 (128->64) + bias + bn2 + relu -> B1 (padded) + B2 (plain) ----
    {
        int p = tid & 63, ln = tid >> 6;
        u64 acc[4] = {0ULL, 0ULL, 0ULL, 0ULL};
        const ulonglong2* Abase = (const ulonglong2*)(sm + L_A + (size_t)ln * 128 * 8);
#pragma unroll 4
        for (int cc = 0; cc < 128; cc++) {
            u64 wd = dup2(sm[L_W + cc * 64 + p]);
            ulonglong2 u0 = Abase[cc * 2];
            ulonglong2 u1 = Abase[cc * 2 + 1];
            fma2(acc[0], wd, u0.x);
            fma2(acc[1], wd, u0.y);
            fma2(acc[2], wd, u1.x);
            fma2(acc[3], wd, u1.y);
        }
        float s2 = sm[L_CONST + 64 + p], o2 = sm[L_CONST + 128 + p];
        float bb = sm[L_CONST + p];
        float* B1row = sm + L_B1 + (ln * 64 + p) * 12;
        float* B2row = sm + L_B2 + (ln * 64 + p) * 8;
        B1row[0] = 0.f; B1row[9] = 0.f;
#pragma unroll
        for (int pr = 0; pr < 4; pr++) {
            float2 v = unpack2(acc[pr]);
            float va = fmaxf((v.x + bb) * s2 + o2, 0.f);
            float vb = fmaxf((v.y + bb) * s2 + o2, 0.f);
            B1row[1 + 2 * pr] = va;
            B1row[2 + 2 * pr] = vb;
            *(float2*)(B2row + 2 * pr) = make_float2(va, vb);
        }
    }
    __syncthreads();

    // ---- stage W2 ----
    {
        float4* wd = (float4*)(sm + L_W);
        const float4* ws = (const float4*)g_w2t;
#pragma unroll
        for (int r = 0; r < 12; r++) wd[tid + r * 256] = ws[tid + r * 256];
    }
    __syncthreads();

    // ---- conv2 (3-tap, 64->64) f32x2 + bias + bn3 + relu -> C ----
    {
        int q = tid & 63, ln = tid >> 6;
        u64 acc2[4] = {0ULL, 0ULL, 0ULL, 0ULL};
#pragma unroll 2
        for (int i = 0; i < 64; i++) {
            u64 W0 = dup2(sm[L_W + (i * 3 + 0) * 64 + q]);
            u64 W1 = dup2(sm[L_W + (i * 3 + 1) * 64 + q]);
            u64 W2 = dup2(sm[L_W + (i * 3 + 2) * 64 + q]);
            const float* Br = sm + L_B1 + (ln * 64 + i) * 12;
            ulonglong2 pA = *(const ulonglong2*)Br;
            ulonglong2 pB = *(const ulonglong2*)(Br + 4);
            u64 P4 = *(const u64*)(Br + 8);
            const ulonglong2* Qr = (const ulonglong2*)(sm + L_B2 + (ln * 64 + i) * 8);
            ulonglong2 qA = Qr[0], qB = Qr[1];
            u64 P[5] = {pA.x, pA.y, pB.x, pB.y, P4};
            u64 Q[4] = {qA.x, qA.y, qB.x, qB.y};
#pragma unroll
            for (int pr = 0; pr < 4; pr++) {
                fma2(acc2[pr], W0, P[pr]);
                fma2(acc2[pr], W1, Q[pr]);
                fma2(acc2[pr], W2, P[pr + 1]);
            }
        }
        __syncthreads();                               // all reads of B done
        float s3 = sm[L_CONST + 256 + q], o3v = sm[L_CONST + 320 + q];
        float bb = sm[L_CONST + 192 + q];
        float* Crow = sm + L_C + (ln * 64 + q) * 8;    // C aliases A (dead)
#pragma unroll
        for (int pr = 0; pr < 4; pr++) {
            float2 v = unpack2(acc2[pr]);
            Crow[2 * pr]     = fmaxf((v.x + bb) * s3 + o3v, 0.f);
            Crow[2 * pr + 1] = fmaxf((v.y + bb) * s3 + o3v, 0.f);
        }
    }
    __syncthreads();

    // ---- stage W3 ----
    {
        float4* wd = (float4*)(sm + L_W);
        const float4* ws = (const float4*)g_w3t;
#pragma unroll
        for (int r = 0; r < 8; r++) wd[tid + r * 256] = ws[tid + r * 256];
    }
    __syncthreads();

    // ---- conv3 (64->128) + residual + relu + fc2 partial ----
    {
        int o = tid & 63, ln = tid >> 6;         // handles o and o+64
        u64 acc[2][4];
#pragma unroll
        for (int a = 0; a < 2; a++)
#pragma unroll
            for (int pr = 0; pr < 4; pr++) acc[a][pr] = 0ULL;
#pragma unroll 2
        for (int q = 0; q < 64; q++) {
            u64 w0 = dup2(sm[L_W + q * 128 + o]);
            u64 w1 = dup2(sm[L_W + q * 128 + o + 64]);
            const ulonglong2* Crow = (const ulonglong2*)(sm + L_C + (ln * 64 + q) * 8);
            ulonglong2 u0 = Crow[0], u1 = Crow[1];
            fma2(acc[0][0], w0, u0.x); fma2(acc[0][1], w0, u0.y);
            fma2(acc[0][2], w0, u1.x); fma2(acc[0][3], w0, u1.y);
            fma2(acc[1][0], w1, u0.x); fma2(acc[1][1], w1, u0.y);
            fma2(acc[1][2], w1, u1.x); fma2(acc[1][3], w1, u1.y);
        }
#pragma unroll
        for (int k = 0; k < 2; k++) {
            int oo = o + 64 * k;
            float bb = sm[L_CONST + 384 + oo];
            const float* X = sm + L_XP + (ln * 128 + oo) * 8;
            const float* fw = sm + L_CONST + 768 + oo * 8;
            float lsum = 0.f;
#pragma unroll
            for (int pr = 0; pr < 4; pr++) {
                float2 v = unpack2(acc[k][pr]);
                float v0 = fmaxf(X[2 * pr]     + v.x + bb, 0.f);
                float v1 = fmaxf(X[2 * pr + 1] + v.y + bb, 0.f);
                lsum += v0 * fw[2 * pr] + v1 * fw[2 * pr + 1];
            }
            sm[L_RED + ln * 128 + oo] = lsum;          // RED aliases B1 (dead)
        }
    }
    __syncthreads();

    // ---- reduce 128 partials per line ----
    if (tid < 128) {
        int l2 = tid >> 5, lane = tid & 31;
        float s = sm[L_RED + l2 * 128 + lane]
                + sm[L_RED + l2 * 128 + lane + 32]
                + sm[L_RED + l2 * 128 + lane + 64]
                + sm[L_RED + l2 * 128 + lane + 96];
#pragma unroll
        for (int off = 16; off > 0; off >>= 1)
            s += __shfl_xor_sync(0xffffffffu, s, off);
        if (lane == 0) out[n0 + l2] = s + fc2b[0];
    }
}

// ---------------------------------------------------------------------------
extern "C" void kernel_launch(void* const* d_in, const int* in_sizes, int n_in,
                              void* d_out, int out_size) {
    const float* feature = (const float*)d_in[0];
    const float* lines   = (const float*)d_in[1];
    const float* fc1_w   = (const float*)d_in[2];
    const float* fc1_b   = (const float*)d_in[3];
    const float* bn1g = (const float*)d_in[4];
    const float* bn1b = (const float*)d_in[5];
    const float* bn1m = (const float*)d_in[6];
    const float* bn1v = (const float*)d_in[7];
    const float* c1w  = (const float*)d_in[8];
    const float* c1b  = (const float*)d_in[9];
    const float* bn2g = (const float*)d_in[10];
    const float* bn2b = (const float*)d_in[11];
    const float* bn2m = (const float*)d_in[12];
    const float* bn2v = (const float*)d_in[13];
    const float* c2w  = (const float*)d_in[14];
    const float* c2b  = (const float*)d_in[15];
    const float* bn3g = (const float*)d_in[16];
    const float* bn3b = (const float*)d_in[17];
    const float* bn3m = (const float*)d_in[18];
    const float* bn3v = (const float*)d_in[19];
    const float* c3w  = (const float*)d_in[20];
    const float* c3b  = (const float*)d_in[21];
    const float* fc2w = (const float*)d_in[22];
    const float* fc2b = (const float*)d_in[23];
    float* out = (float*)d_out;

    cudaFuncSetAttribute(k_fc1, cudaFuncAttributeMaxDynamicSharedMemorySize,
                         FC1_SMEM_BYTES);
    cudaFuncSetAttribute(k_lines, cudaFuncAttributeMaxDynamicSharedMemorySize,
                         K2_SMEM_BYTES);

    k_prep<<<64, 256>>>(fc1_w,
                        bn1g, bn1b, bn1m, bn1v, c1w, c1b,
                        bn2g, bn2b, bn2m, bn2v, c2w, c2b,
                        bn3g, bn3b, bn3m, bn3v, c3w, c3b, fc2w);

    dim3 g1(HW * HW / 128, NB);
    k_fc1<<<g1, 256, FC1_SMEM_BYTES>>>(feature, fc1_b);

    k_lines<<<NLINES / 4, 256, K2_SMEM_BYTES>>>(lines, fc2b, out);
}